// round 3
// baseline (speedup 1.0000x reference)
#include <cuda_runtime.h>

#define TT     32768
#define HID    100
#define DIN    300
#define G4     400
#define CH     64                 // chaser chunk (timesteps)
#define NCHUNK (TT / CH)          // 512
#define NCHASE 8
#define P0CH   32                 // layer0 progress publish interval

// ---------------- scratch (static device allocations; no cudaMalloc) -------
__device__ float g_xp0[TT * G4];          // input projection, layer 0 (permuted: [t][u*4+g])
__device__ float g_xp1[TT * G4];          // input projection, layer 1 (permuted)
__device__ float g_h0[TT * HID];          // layer-0 hidden sequence [t][u]
__device__ float g_h1[TT * HID];          // layer-1 hidden sequence [t][u]
__device__ float g_WcT[DIN * G4];         // fused (W_ih_l0 @ W_inp), transposed [k][j]
__device__ float g_bc[G4];                // fused bias for layer-0 gates
__device__ float g_WoutT[HID * DIN];      // W_out transposed [k][d]
__device__ volatile int g_prog0;          // layer-0 progress (steps completed)
__device__ volatile int g_flag1[NCHUNK];  // xp1 chunk-ready flags

typedef unsigned long long u64;

// ---------------- f32x2 packed helpers (Blackwell) -------------------------
__device__ __forceinline__ u64 ffma2(u64 a, u64 b, u64 c) {
    u64 d;
    asm("fma.rn.f32x2 %0, %1, %2, %3;" : "=l"(d) : "l"(a), "l"(b), "l"(c));
    return d;
}
__device__ __forceinline__ u64 addf2(u64 a, u64 b) {
    u64 d;
    asm("add.rn.f32x2 %0, %1, %2;" : "=l"(d) : "l"(a), "l"(b));
    return d;
}
__device__ __forceinline__ u64 packf2(float lo, float hi) {
    u64 v;
    asm("mov.b64 %0, {%1, %2};" : "=l"(v) : "f"(lo), "f"(hi));
    return v;
}
__device__ __forceinline__ void unpack2(u64 v, float& lo, float& hi) {
    asm("mov.b64 {%0, %1}, %2;" : "=f"(lo), "=f"(hi) : "l"(v));
}

// Accurate, overflow-safe activations (MUFU-based, rel err ~1e-6)
__device__ __forceinline__ float sig_(float x) {
    return __fdividef(1.0f, 1.0f + __expf(-x));
}
__device__ __forceinline__ float tanh_(float x) {
    return __fdividef(2.0f, 1.0f + __expf(-2.0f * x)) - 1.0f;
}

// permuted xp storage slot for gate-row j (j = g*100+u  ->  u*4+g)
__device__ __forceinline__ int xp_perm(int j) { return (j % 100) * 4 + (j / 100); }

// ---------------- kernel 0: prep (fused weights, transposes, flag reset) ---
__global__ void prep_kernel(const float* __restrict__ Wih0,
                            const float* __restrict__ Winp,
                            const float* __restrict__ binp,
                            const float* __restrict__ bih0,
                            const float* __restrict__ bhh0,
                            const float* __restrict__ Wout) {
    int tid = blockIdx.x * blockDim.x + threadIdx.x;
    if (tid < G4 * DIN) {                               // WcT[k][j] = sum_m Wih0[j,m]*Winp[m,k]
        int j = tid / DIN, k = tid % DIN;
        float s = 0.f;
        for (int m = 0; m < HID; m++)
            s = fmaf(Wih0[j * HID + m], Winp[m * DIN + k], s);
        g_WcT[k * G4 + j] = s;
    } else if (tid < G4 * DIN + G4) {                   // bc[j]
        int j = tid - G4 * DIN;
        float s = bih0[j] + bhh0[j];
        for (int m = 0; m < HID; m++)
            s = fmaf(Wih0[j * HID + m], binp[m], s);
        g_bc[j] = s;
    } else if (tid < G4 * DIN + G4 + DIN * HID) {       // WoutT[k][d]
        int q = tid - (G4 * DIN + G4);
        int d = q / HID, k = q % HID;
        g_WoutT[k * DIN + d] = Wout[d * HID + k];
    } else if (tid < G4 * DIN + G4 + DIN * HID + NCHUNK + 1) {
        int q = tid - (G4 * DIN + G4 + DIN * HID);
        if (q < NCHUNK) g_flag1[q] = 0;
        else            g_prog0 = 0;
    }
}

// ---------------- kernel 1: xp0 = inputs @ WcT + bc  (fully parallel) ------
__global__ __launch_bounds__(400) void xp0_gemm(const float* __restrict__ inputs) {
    __shared__ __align__(16) float inpT[DIN * 32];      // transposed tile [k][t]
    const int t0 = blockIdx.x * 32;
    const int j  = threadIdx.x;                         // one gate row each

    for (int idx = j; idx < 32 * DIN; idx += 400) {
        int t = idx / DIN, k = idx % DIN;
        inpT[k * 32 + t] = inputs[(t0 + t) * DIN + k];
    }
    __syncthreads();

    const float bcj = g_bc[j];
    u64 acc[16];
    #pragma unroll
    for (int tp = 0; tp < 16; tp++) acc[tp] = packf2(bcj, bcj);

    #pragma unroll 4
    for (int k = 0; k < DIN; k++) {
        float w = g_WcT[k * G4 + j];
        u64 w2 = packf2(w, w);
        const u64* row2 = (const u64*)(inpT + k * 32);
        #pragma unroll
        for (int tp = 0; tp < 16; tp++)
            acc[tp] = ffma2(w2, row2[tp], acc[tp]);
    }
    const int sidx = xp_perm(j);
    #pragma unroll
    for (int tp = 0; tp < 16; tp++) {
        float lo, hi; unpack2(acc[tp], lo, hi);
        g_xp0[(t0 + 2 * tp + 0) * G4 + sidx] = lo;
        g_xp0[(t0 + 2 * tp + 1) * G4 + sidx] = hi;
    }
}

// ---------------- persistent scan kernel -----------------------------------
// block 0: layer-0 scan | block 1: layer-1 scan | blocks 2..9: xp1 chasers
//
// Scan thread layout: tid = u*4 + g  (u = hidden unit 0..99, g = gate i/f/g/o).
// All 4 gates of a unit live in 4 adjacent lanes -> act exchange via 4 SHFLs,
// c/h update computed redundantly by all 4 lanes, ONE __syncthreads per step.
template <int L>
__device__ void layer_scan(const float* __restrict__ Whh,
                           const float* __restrict__ xp_src,
                           float* __restrict__ h_dst,
                           float* __restrict__ out) {
    __shared__ __align__(16) float hs[2][104];          // double-buffered h
    const int tid  = threadIdx.x;
    const int u    = tid >> 2;
    const int g    = tid & 3;
    const int row  = g * HID + u;                       // gate row in Whh / gate order
    const int lane = tid & 31;
    const int base = lane & ~3;
    const unsigned mask = (tid < 384) ? 0xFFFFFFFFu : 0x0000FFFFu;  // warp 12 has 16 lanes

    // recurrent weights register-resident, f32x2-packed over k
    u64 w[50];
    const float2* wrow = (const float2*)(Whh + row * HID);
    #pragma unroll
    for (int kk = 0; kk < 50; kk++) {
        float2 p = wrow[kk];
        w[kk] = packf2(p.x, p.y);
    }

    if (tid < HID) hs[0][tid] = 0.f;
    __syncthreads();

    float c = 0.f, hcur = 0.f;
    float xp_cur = 0.f, xp_nxt = 0.f;

    for (int t = 0; t < TT; t++) {
        if ((t & (CH - 1)) == 0) {
            if (L == 1) {                               // wait this chunk + next (covers prefetch)
                if (tid == 0) {
                    int c0 = t >> 6;
                    int c1 = (c0 + 1 < NCHUNK) ? c0 + 1 : NCHUNK - 1;
                    while (g_flag1[c0] == 0 || g_flag1[c1] == 0) __nanosleep(128);
                    __threadfence();
                }
                __syncthreads();
            }
            if (t == 0) {                               // xp pipeline warmup
                xp_cur = xp_src[tid];
                xp_nxt = xp_src[G4 + tid];
            }
        }

        // recurrent matvec: 25 LDS.128 + 50 FFMA2 in 4 independent chains
        const ulonglong2* hv = (const ulonglong2*)hs[t & 1];
        u64 a0 = 0ull, a1 = 0ull, a2 = 0ull, a3 = 0ull;
        #pragma unroll
        for (int q = 0; q < 24; q += 2) {
            ulonglong2 v0 = hv[q];
            ulonglong2 v1 = hv[q + 1];
            a0 = ffma2(w[2 * q + 0], v0.x, a0);
            a1 = ffma2(w[2 * q + 1], v0.y, a1);
            a2 = ffma2(w[2 * q + 2], v1.x, a2);
            a3 = ffma2(w[2 * q + 3], v1.y, a3);
        }
        {
            ulonglong2 v = hv[24];
            a0 = ffma2(w[48], v.x, a0);
            a1 = ffma2(w[49], v.y, a1);
        }
        // prefetch xp[t+2] (2-step pipeline covers DRAM latency)
        float xp_fut = (t + 2 < TT) ? xp_src[(t + 2) * G4 + tid] : 0.f;

        float lo, hi; unpack2(addf2(addf2(a0, a1), addf2(a2, a3)), lo, hi);
        float pre = xp_cur + (lo + hi);
        float a = (g == 2) ? tanh_(pre) : sig_(pre);

        // gather the unit's 4 gate activations within the warp
        float ai = __shfl_sync(mask, a, base + 0);
        float af = __shfl_sync(mask, a, base + 1);
        float ag = __shfl_sync(mask, a, base + 2);
        float ao = __shfl_sync(mask, a, base + 3);

        c    = fmaf(af, c, ai * ag);                    // all 4 lanes keep identical c
        hcur = ao * tanh_(c);

        if (g == 0) {
            hs[(t + 1) & 1][u] = hcur;
            h_dst[t * HID + u] = hcur;
            if (L == 0 && ((t & (P0CH - 1)) == (P0CH - 1))) __threadfence();
        }
        __syncthreads();                                // single barrier per step

        if (L == 0 && ((t & (P0CH - 1)) == (P0CH - 1)) && tid == 0)
            g_prog0 = t + 1;

        xp_cur = xp_nxt;
        xp_nxt = xp_fut;
    }

    if (g == 0) {                                       // h_n / c_n tails
        out[TT * DIN + L * HID + u]           = hcur;
        out[TT * DIN + 2 * HID + L * HID + u] = c;
    }
}

__device__ void chaser(int ci,
                       const float* __restrict__ Wih1,
                       const float* __restrict__ bih1,
                       const float* __restrict__ bhh1) {
    __shared__ __align__(16) float h0s[CH * HID];       // 25.6 KB
    const int j = threadIdx.x;                          // gate row

    u64 w[50];
    const float2* wrow = (const float2*)(Wih1 + j * HID);
    #pragma unroll
    for (int kk = 0; kk < 50; kk++) {
        float2 p = wrow[kk];
        w[kk] = packf2(p.x, p.y);
    }
    const float bj   = bih1[j] + bhh1[j];
    const int   sidx = xp_perm(j);
    const ulonglong2* h2 = (const ulonglong2*)h0s;

    for (int cidx = ci; cidx < NCHUNK; cidx += NCHASE) {
        const int t0 = cidx * CH;
        if (j == 0) {
            while (g_prog0 < t0 + CH) __nanosleep(256);
            __threadfence();
        }
        __syncthreads();
        {   // vectorized copy of 64 steps of h0 into smem
            const float4* src = (const float4*)(g_h0 + t0 * HID);
            float4*       dst = (float4*)h0s;
            for (int idx = j; idx < CH * HID / 4; idx += G4)
                dst[idx] = src[idx];
        }
        __syncthreads();

        for (int t = 0; t < CH; t++) {
            const ulonglong2* hv = h2 + t * 25;
            u64 a0 = 0ull, a1 = 0ull, a2 = 0ull, a3 = 0ull;
            #pragma unroll
            for (int q = 0; q < 24; q += 2) {
                ulonglong2 v0 = hv[q];
                ulonglong2 v1 = hv[q + 1];
                a0 = ffma2(w[2 * q + 0], v0.x, a0);
                a1 = ffma2(w[2 * q + 1], v0.y, a1);
                a2 = ffma2(w[2 * q + 2], v1.x, a2);
                a3 = ffma2(w[2 * q + 3], v1.y, a3);
            }
            {
                ulonglong2 v = hv[24];
                a0 = ffma2(w[48], v.x, a0);
                a1 = ffma2(w[49], v.y, a1);
            }
            float lo, hi; unpack2(addf2(addf2(a0, a1), addf2(a2, a3)), lo, hi);
            g_xp1[(t0 + t) * G4 + sidx] = bj + (lo + hi);
        }
        __threadfence();
        __syncthreads();
        if (j == 0) g_flag1[cidx] = 1;
    }
}

__global__ __launch_bounds__(400) void scan_kernel(const float* __restrict__ Whh0,
                                                   const float* __restrict__ Wih1,
                                                   const float* __restrict__ Whh1,
                                                   const float* __restrict__ bih1,
                                                   const float* __restrict__ bhh1,
                                                   float* __restrict__ out) {
    if (blockIdx.x == 0)      layer_scan<0>(Whh0, g_xp0, g_h0, out);
    else if (blockIdx.x == 1) layer_scan<1>(Whh1, g_xp1, g_h1, out);
    else                      chaser(blockIdx.x - 2, Wih1, bih1, bhh1);
}

// ---------------- kernel 3: outputs = h1_seq @ W_out^T + b_out -------------
__global__ __launch_bounds__(320) void out_gemm(const float* __restrict__ bout,
                                                float* __restrict__ out) {
    __shared__ __align__(16) float h1s[32 * HID];
    const int t0 = blockIdx.x * 32;
    const int d  = threadIdx.x;

    {
        const float4* src = (const float4*)(g_h1 + t0 * HID);
        float4*       dst = (float4*)h1s;
        for (int idx = threadIdx.x; idx < 32 * HID / 4; idx += 320)
            dst[idx] = src[idx];
    }
    __syncthreads();

    if (d < DIN) {
        u64 w[50];
        #pragma unroll
        for (int kk = 0; kk < 50; kk++)
            w[kk] = packf2(g_WoutT[(2 * kk) * DIN + d], g_WoutT[(2 * kk + 1) * DIN + d]);
        const float bd = bout[d];
        const ulonglong2* h2 = (const ulonglong2*)h1s;
        for (int t = 0; t < 32; t++) {
            const ulonglong2* hv = h2 + t * 25;
            u64 a0 = 0ull, a1 = 0ull;
            #pragma unroll
            for (int q = 0; q < 25; q++) {
                ulonglong2 v = hv[q];
                a0 = ffma2(w[2 * q + 0], v.x, a0);
                a1 = ffma2(w[2 * q + 1], v.y, a1);
            }
            float lo, hi; unpack2(addf2(a0, a1), lo, hi);
            out[(t0 + t) * DIN + d] = bd + (lo + hi);
        }
    }
}

// ---------------- launch ----------------------------------------------------
extern "C" void kernel_launch(void* const* d_in, const int* in_sizes, int n_in,
                              void* d_out, int out_size) {
    (void)in_sizes; (void)n_in; (void)out_size;
    const float* inputs = (const float*)d_in[0];
    const float* W_inp  = (const float*)d_in[1];
    const float* b_inp  = (const float*)d_in[2];
    const float* Wih0   = (const float*)d_in[3];
    const float* Whh0   = (const float*)d_in[4];
    const float* bih0   = (const float*)d_in[5];
    const float* bhh0   = (const float*)d_in[6];
    const float* Wih1   = (const float*)d_in[7];
    const float* Whh1   = (const float*)d_in[8];
    const float* bih1   = (const float*)d_in[9];
    const float* bhh1   = (const float*)d_in[10];
    const float* Wout   = (const float*)d_in[11];
    const float* bout   = (const float*)d_in[12];
    float* out = (float*)d_out;

    prep_kernel<<<(G4 * DIN + G4 + DIN * HID + NCHUNK + 1 + 255) / 256, 256>>>(
        Wih0, W_inp, b_inp, bih0, bhh0, Wout);
    xp0_gemm<<<TT / 32, 400>>>(inputs);
    scan_kernel<<<2 + NCHASE, 400>>>(Whh0, Wih1, Whh1, bih1, bhh1, out);
    out_gemm<<<TT / 32, 320>>>(bout, out);
}

// round 4
// speedup vs baseline: 1.0302x; 1.0302x over previous
#include <cuda_runtime.h>

#define TT     32768
#define HID    100
#define DIN    300
#define G4     400
#define XTILE  32                  // xp0 producer tile (timesteps)
#define NXTILE (TT / XTILE)        // 1024
#define NXPB   64                  // xp0 producer blocks
#define CH     64                  // chaser chunk (timesteps)
#define NCHUNK (TT / CH)           // 512
#define NCHASE 8

// ---------------- scratch (static device allocations) ----------------------
__device__ float g_xp0[(TT + 2) * G4];    // layer-0 input proj, permuted [t][u*4+g], +2 pad
__device__ float g_xp1[(TT + 2) * G4];    // layer-1 input proj, permuted, +2 pad
__device__ float g_h0[TT * HID];          // layer-0 hidden sequence [t][u]
__device__ float g_h1[TT * HID];          // layer-1 hidden sequence [t][u]
__device__ float g_WcT[DIN * G4];         // fused (W_ih_l0 @ W_inp)^T [k][j], g-rows x2
__device__ float g_bc[G4];                // fused layer-0 gate bias, g-rows x2
__device__ float g_WoutT[HID * DIN];      // W_out transposed [k][d]
__device__ volatile int g_prog0;          // layer-0 progress (steps completed)
__device__ volatile int g_flag0[NXTILE];  // xp0 tile-ready flags
__device__ volatile int g_flag1[NCHUNK];  // xp1 chunk-ready flags

typedef unsigned long long u64;

// ---------------- f32x2 packed helpers --------------------------------------
__device__ __forceinline__ u64 ffma2(u64 a, u64 b, u64 c) {
    u64 d;
    asm("fma.rn.f32x2 %0, %1, %2, %3;" : "=l"(d) : "l"(a), "l"(b), "l"(c));
    return d;
}
__device__ __forceinline__ u64 addf2(u64 a, u64 b) {
    u64 d;
    asm("add.rn.f32x2 %0, %1, %2;" : "=l"(d) : "l"(a), "l"(b));
    return d;
}
__device__ __forceinline__ u64 packf2(float lo, float hi) {
    u64 v;
    asm("mov.b64 %0, {%1, %2};" : "=l"(v) : "f"(lo), "f"(hi));
    return v;
}
__device__ __forceinline__ void unpack2(u64 v, float& lo, float& hi) {
    asm("mov.b64 {%0, %1}, %2;" : "=f"(lo), "=f"(hi) : "l"(v));
}

// branchless logistic (2 MUFU, overflow-safe)
__device__ __forceinline__ float sig_(float x) {
    return __fdividef(1.0f, 1.0f + __expf(-x));
}

// permuted xp slot for gate-row j (j = g*100+u -> u*4+g)
__device__ __forceinline__ int xp_perm(int j) { return (j % 100) * 4 + (j / 100); }

// ---------------- kernel 0: prep --------------------------------------------
__global__ void prep_kernel(const float* __restrict__ Wih0,
                            const float* __restrict__ Winp,
                            const float* __restrict__ binp,
                            const float* __restrict__ bih0,
                            const float* __restrict__ bhh0,
                            const float* __restrict__ Wout) {
    int tid = blockIdx.x * blockDim.x + threadIdx.x;
    if (tid < G4 * DIN) {                               // WcT[k][j] (g-rows pre-scaled x2)
        int j = tid / DIN, k = tid % DIN;
        float s = 0.f;
        for (int m = 0; m < HID; m++)
            s = fmaf(Wih0[j * HID + m], Winp[m * DIN + k], s);
        if (j >= 200 && j < 300) s *= 2.f;
        g_WcT[k * G4 + j] = s;
    } else if (tid < G4 * DIN + G4) {                   // bc[j] (g-rows x2)
        int j = tid - G4 * DIN;
        float s = bih0[j] + bhh0[j];
        for (int m = 0; m < HID; m++)
            s = fmaf(Wih0[j * HID + m], binp[m], s);
        if (j >= 200 && j < 300) s *= 2.f;
        g_bc[j] = s;
    } else if (tid < G4 * DIN + G4 + DIN * HID) {       // WoutT[k][d]
        int q = tid - (G4 * DIN + G4);
        int d = q / HID, k = q % HID;
        g_WoutT[k * DIN + d] = Wout[d * HID + k];
    } else if (tid < G4 * DIN + G4 + DIN * HID + NCHUNK + NXTILE + 1) {
        int q = tid - (G4 * DIN + G4 + DIN * HID);
        if (q < NCHUNK)            g_flag1[q] = 0;
        else if (q < NCHUNK + NXTILE) g_flag0[q - NCHUNK] = 0;
        else                       g_prog0 = 0;
    }
}

// ---------------- xp0 producer (blocks 10..73 of the persistent kernel) ----
__device__ void xp0_producer(int pb, const float* __restrict__ inputs) {
    __shared__ __align__(16) float inpT[DIN * XTILE];   // transposed tile [k][t]
    const int j    = threadIdx.x;
    const int sidx = xp_perm(j);
    const float bcj = g_bc[j];

    for (int ti = pb; ti < NXTILE; ti += NXPB) {
        const int t0 = ti * XTILE;
        for (int idx = j; idx < XTILE * DIN; idx += G4) {
            int t = idx / DIN, k = idx % DIN;
            inpT[k * XTILE + t] = inputs[(t0 + t) * DIN + k];
        }
        __syncthreads();

        u64 acc[16];
        #pragma unroll
        for (int tp = 0; tp < 16; tp++) acc[tp] = packf2(bcj, bcj);

        #pragma unroll 4
        for (int k = 0; k < DIN; k++) {
            float wv = g_WcT[k * G4 + j];
            u64 w2 = packf2(wv, wv);
            const u64* row2 = (const u64*)(inpT + k * XTILE);
            #pragma unroll
            for (int tp = 0; tp < 16; tp++)
                acc[tp] = ffma2(w2, row2[tp], acc[tp]);
        }
        #pragma unroll
        for (int tp = 0; tp < 16; tp++) {
            float lo, hi; unpack2(acc[tp], lo, hi);
            g_xp0[(t0 + 2 * tp + 0) * G4 + sidx] = lo;
            g_xp0[(t0 + 2 * tp + 1) * G4 + sidx] = hi;
        }
        __threadfence();
        __syncthreads();                                // also protects inpT reuse
        if (j == 0) g_flag0[ti] = 1;
    }
}

// ---------------- layer scan (blocks 0 and 1) -------------------------------
// tid = u*4 + g. All 4 gates of unit u in adjacent lanes of ONE warp:
// act exchange = 4 intra-warp SHFLs, c/h redundant per lane, ONE bar per step.
// Activation is fully branchless: a = s*sig(pre)+b, gate-g rows prescaled x2.
template <int L>
__device__ void layer_scan(const float* __restrict__ Whh,
                           const float* __restrict__ xp_src,
                           float* __restrict__ h_dst,
                           float* __restrict__ out) {
    __shared__ __align__(16) float hs[2][104];          // double-buffered h
    const int tid  = threadIdx.x;
    const int u    = tid >> 2;
    const int g    = tid & 3;
    const int row  = g * HID + u;
    const int base = (tid & 31) & ~3;
    const unsigned mask = (tid < 384) ? 0xFFFFFFFFu : 0x0000FFFFu;
    const float ws = (g == 2) ? 2.f : 1.f;              // gate-g prescale
    const float sg = (g == 2) ? 2.f : 1.f;              // act = sg*sig + bg
    const float bg = (g == 2) ? -1.f : 0.f;

    u64 w[50];
    const float2* wrow = (const float2*)(Whh + row * HID);
    #pragma unroll
    for (int kk = 0; kk < 50; kk++) {
        float2 p = wrow[kk];
        w[kk] = packf2(p.x * ws, p.y * ws);
    }
    if (tid < HID) hs[0][tid] = 0.f;
    __syncthreads();

    float c = 0.f, hcur = 0.f;
    float xp_cur = 0.f, xp_nxt = 0.f;
    const float* xp_p = xp_src + tid;                   // running pointer (step t)
    float* hd = h_dst + u;

    for (int cb = 0; cb < TT / 32; cb++) {
        // readiness wait (outside the hot loop)
        if (tid == 0) {
            if (L == 0) {
                int f1 = (cb + 1 < NXTILE) ? cb + 1 : NXTILE - 1;
                while (!(g_flag0[cb] && g_flag0[f1])) __nanosleep(64);
            } else {
                int c0 = cb >> 1;
                int c1 = (c0 + 1 < NCHUNK) ? c0 + 1 : NCHUNK - 1;
                while (!(g_flag1[c0] && g_flag1[c1])) __nanosleep(64);
            }
            __threadfence();
        }
        __syncthreads();
        if (cb == 0) {                                  // xp pipeline warmup
            xp_cur = xp_p[0];
            xp_nxt = xp_p[G4];
        }

        for (int tt = 0; tt < 32; tt++) {
            const int t = cb * 32 + tt;
            const ulonglong2* hv = (const ulonglong2*)hs[t & 1];
            u64 a0 = 0ull, a1 = 0ull;
            #pragma unroll
            for (int q = 0; q < 25; q++) {
                ulonglong2 v = hv[q];
                a0 = ffma2(w[2 * q + 0], v.x, a0);
                a1 = ffma2(w[2 * q + 1], v.y, a1);
            }
            float xp_fut = xp_p[2 * G4];                // prefetch t+2 (padded array)

            float lo, hi; unpack2(addf2(a0, a1), lo, hi);
            float pre = xp_cur + (lo + hi);
            float a = fmaf(sg, sig_(pre), bg);          // branchless i/f/o: sig, g: tanh

            float ai  = __shfl_sync(mask, a, base + 0);
            float af  = __shfl_sync(mask, a, base + 1);
            float ag_ = __shfl_sync(mask, a, base + 2);
            float ao  = __shfl_sync(mask, a, base + 3);

            c = fmaf(af, c, ai * ag_);                  // identical in all 4 lanes
            float th = __fdividef(2.f, 1.f + __expf(-2.f * c)) - 1.f;
            hcur = ao * th;

            if (g == 0) {
                hs[(t + 1) & 1][u] = hcur;
                hd[0] = hcur;
            }
            __syncthreads();                            // single barrier per step

            xp_cur = xp_nxt;
            xp_nxt = xp_fut;
            xp_p  += G4;
            hd    += HID;
        }

        if (L == 0) {                                   // publish progress per 32 steps
            __threadfence();
            __syncthreads();
            if (tid == 0) g_prog0 = (cb + 1) * 32;
        }
    }

    if (g == 0) {                                       // h_n / c_n tails
        out[TT * DIN + L * HID + u]           = hcur;
        out[TT * DIN + 2 * HID + L * HID + u] = c;
    }
}

// ---------------- chaser: xp1 = h0 @ Wih1^T + b (blocks 2..9) --------------
__device__ void chaser(int ci,
                       const float* __restrict__ Wih1,
                       const float* __restrict__ bih1,
                       const float* __restrict__ bhh1) {
    __shared__ __align__(16) float h0s[CH * HID];       // 25.6 KB
    const int j = threadIdx.x;
    const float ws = (j >= 200 && j < 300) ? 2.f : 1.f; // gate-g prescale

    u64 w[50];
    const float2* wrow = (const float2*)(Wih1 + j * HID);
    #pragma unroll
    for (int kk = 0; kk < 50; kk++) {
        float2 p = wrow[kk];
        w[kk] = packf2(p.x * ws, p.y * ws);
    }
    const float bj   = (bih1[j] + bhh1[j]) * ws;
    const int   sidx = xp_perm(j);
    const ulonglong2* h2 = (const ulonglong2*)h0s;

    for (int cidx = ci; cidx < NCHUNK; cidx += NCHASE) {
        const int t0 = cidx * CH;
        if (j == 0) {
            while (g_prog0 < t0 + CH) __nanosleep(128);
            __threadfence();
        }
        __syncthreads();
        {
            const float4* src = (const float4*)(g_h0 + t0 * HID);
            float4*       dst = (float4*)h0s;
            for (int idx = j; idx < CH * HID / 4; idx += G4)
                dst[idx] = src[idx];
        }
        __syncthreads();

        for (int t = 0; t < CH; t++) {
            const ulonglong2* hv = h2 + t * 25;
            u64 a0 = 0ull, a1 = 0ull;
            #pragma unroll 5
            for (int q = 0; q < 25; q++) {
                ulonglong2 v = hv[q];
                a0 = ffma2(w[2 * q + 0], v.x, a0);
                a1 = ffma2(w[2 * q + 1], v.y, a1);
            }
            float lo, hi; unpack2(addf2(a0, a1), lo, hi);
            g_xp1[(t0 + t) * G4 + sidx] = bj + (lo + hi);
        }
        __threadfence();
        __syncthreads();
        if (j == 0) g_flag1[cidx] = 1;
    }
}

// ---------------- persistent kernel -----------------------------------------
__global__ __launch_bounds__(400, 1)
void scan_kernel(const float* __restrict__ inputs,
                 const float* __restrict__ Whh0,
                 const float* __restrict__ Wih1,
                 const float* __restrict__ Whh1,
                 const float* __restrict__ bih1,
                 const float* __restrict__ bhh1,
                 float* __restrict__ out) {
    if (blockIdx.x == 0)       layer_scan<0>(Whh0, g_xp0, g_h0, out);
    else if (blockIdx.x == 1)  layer_scan<1>(Whh1, g_xp1, g_h1, out);
    else if (blockIdx.x < 2 + NCHASE) chaser(blockIdx.x - 2, Wih1, bih1, bhh1);
    else                       xp0_producer(blockIdx.x - 2 - NCHASE, inputs);
}

// ---------------- kernel 2: outputs = h1_seq @ W_out^T + b_out -------------
__global__ __launch_bounds__(320) void out_gemm(const float* __restrict__ bout,
                                                float* __restrict__ out) {
    __shared__ __align__(16) float h1s[32 * HID];
    const int t0 = blockIdx.x * 32;
    const int d  = threadIdx.x;

    {
        const float4* src = (const float4*)(g_h1 + t0 * HID);
        float4*       dst = (float4*)h1s;
        for (int idx = threadIdx.x; idx < 32 * HID / 4; idx += 320)
            dst[idx] = src[idx];
    }
    __syncthreads();

    if (d < DIN) {
        u64 w[50];
        #pragma unroll
        for (int kk = 0; kk < 50; kk++)
            w[kk] = packf2(g_WoutT[(2 * kk) * DIN + d], g_WoutT[(2 * kk + 1) * DIN + d]);
        const float bd = bout[d];
        const ulonglong2* h2 = (const ulonglong2*)h1s;
        for (int t = 0; t < 32; t++) {
            const ulonglong2* hv = h2 + t * 25;
            u64 a0 = 0ull, a1 = 0ull;
            #pragma unroll 5
            for (int q = 0; q < 25; q++) {
                ulonglong2 v = hv[q];
                a0 = ffma2(w[2 * q + 0], v.x, a0);
                a1 = ffma2(w[2 * q + 1], v.y, a1);
            }
            float lo, hi; unpack2(addf2(a0, a1), lo, hi);
            out[(t0 + t) * DIN + d] = bd + (lo + hi);
        }
    }
}

// ---------------- launch ----------------------------------------------------
extern "C" void kernel_launch(void* const* d_in, const int* in_sizes, int n_in,
                              void* d_out, int out_size) {
    (void)in_sizes; (void)n_in; (void)out_size;
    const float* inputs = (const float*)d_in[0];
    const float* W_inp  = (const float*)d_in[1];
    const float* b_inp  = (const float*)d_in[2];
    const float* Wih0   = (const float*)d_in[3];
    const float* Whh0   = (const float*)d_in[4];
    const float* bih0   = (const float*)d_in[5];
    const float* bhh0   = (const float*)d_in[6];
    const float* Wih1   = (const float*)d_in[7];
    const float* Whh1   = (const float*)d_in[8];
    const float* bih1   = (const float*)d_in[9];
    const float* bhh1   = (const float*)d_in[10];
    const float* Wout   = (const float*)d_in[11];
    const float* bout   = (const float*)d_in[12];
    float* out = (float*)d_out;

    int prep_items = G4 * DIN + G4 + DIN * HID + NCHUNK + NXTILE + 1;
    prep_kernel<<<(prep_items + 255) / 256, 256>>>(Wih0, W_inp, b_inp, bih0, bhh0, Wout);
    scan_kernel<<<2 + NCHASE + NXPB, 400>>>(inputs, Whh0, Wih1, Whh1, bih1, bhh1, out);
    out_gemm<<<TT / 32, 320>>>(bout, out);
}

// round 5
// speedup vs baseline: 1.4385x; 1.3963x over previous
#include <cuda_runtime.h>

#define TT     32768
#define HID    100
#define DIN    300
#define THR    200                 // scan block size: 2 gate rows / thread
#define XROW   448                 // padded xp row stride (4*112)
#define XTILE  32                  // xp0 producer tile (timesteps)
#define NXTILE (TT / XTILE)        // 1024
#define NXPB   64                  // xp0 producer blocks
#define CH     64                  // chaser chunk (timesteps)
#define NCHUNK (TT / CH)           // 512
#define NCHASE 8

// ---------------- scratch (static device allocations) ----------------------
__device__ float g_xp0[(TT + 2) * XROW];  // layer-0 input proj, [t][4u+{i,2g,f,o}]
__device__ float g_xp1[(TT + 2) * XROW];  // layer-1 input proj, same layout
__device__ float g_h0[TT * HID];          // layer-0 hidden sequence [t][u]
__device__ float g_h1[TT * HID];          // layer-1 hidden sequence [t][u]
__device__ float g_WcT[DIN * 400];        // fused (W_ih_l0 @ W_inp)^T [k][j], g-rows x2
__device__ float g_bc[400];               // fused layer-0 gate bias, g-rows x2
__device__ float g_WoutT[HID * DIN];      // W_out transposed [k][d]
__device__ volatile int g_prog0;          // layer-0 progress (steps completed)
__device__ volatile int g_flag0[NXTILE];  // xp0 tile-ready flags
__device__ volatile int g_flag1[NCHUNK];  // xp1 chunk-ready flags

typedef unsigned long long u64;

// ---------------- f32x2 packed helpers --------------------------------------
__device__ __forceinline__ u64 ffma2(u64 a, u64 b, u64 c) {
    u64 d;
    asm("fma.rn.f32x2 %0, %1, %2, %3;" : "=l"(d) : "l"(a), "l"(b), "l"(c));
    return d;
}
__device__ __forceinline__ u64 packf2(float lo, float hi) {
    u64 v;
    asm("mov.b64 %0, {%1, %2};" : "=l"(v) : "f"(lo), "f"(hi));
    return v;
}
__device__ __forceinline__ float hsum2(u64 v) {
    float lo, hi;
    asm("mov.b64 {%0, %1}, %2;" : "=f"(lo), "=f"(hi) : "l"(v));
    return lo + hi;
}

// exact-path activations (MUFU exp/rcp, rel err ~1e-6, overflow-safe)
__device__ __forceinline__ float sig_(float x) {
    return __fdividef(1.0f, 1.0f + __expf(-x));
}
__device__ __forceinline__ float tanh_(float x) {
    return __fdividef(2.0f, 1.0f + __expf(-2.0f * x)) - 1.0f;
}

// xp slot for gate-row j: PyTorch gate order i,f,g,o -> per-unit order [i, g, f, o]
__device__ __forceinline__ int xp_slot(int j) {
    int u = j % 100, gg = j / 100;
    int off = (gg == 0) ? 0 : (gg == 1) ? 2 : (gg == 2) ? 1 : 3;
    return 4 * u + off;
}

// ---------------- kernel 0: prep --------------------------------------------
__global__ void prep_kernel(const float* __restrict__ Wih0,
                            const float* __restrict__ Winp,
                            const float* __restrict__ binp,
                            const float* __restrict__ bih0,
                            const float* __restrict__ bhh0,
                            const float* __restrict__ Wout) {
    int tid = blockIdx.x * blockDim.x + threadIdx.x;
    if (tid < 400 * DIN) {                              // WcT[k][j] (g-rows pre-scaled x2)
        int j = tid / DIN, k = tid % DIN;
        float s = 0.f;
        for (int m = 0; m < HID; m++)
            s = fmaf(Wih0[j * HID + m], Winp[m * DIN + k], s);
        if (j >= 200 && j < 300) s *= 2.f;
        g_WcT[k * 400 + j] = s;
    } else if (tid < 400 * DIN + 400) {                 // bc[j] (g-rows x2)
        int j = tid - 400 * DIN;
        float s = bih0[j] + bhh0[j];
        for (int m = 0; m < HID; m++)
            s = fmaf(Wih0[j * HID + m], binp[m], s);
        if (j >= 200 && j < 300) s *= 2.f;
        g_bc[j] = s;
    } else if (tid < 400 * DIN + 400 + DIN * HID) {     // WoutT[k][d]
        int q = tid - (400 * DIN + 400);
        int d = q / HID, k = q % HID;
        g_WoutT[k * DIN + d] = Wout[d * HID + k];
    } else if (tid < 400 * DIN + 400 + DIN * HID + NCHUNK + NXTILE + 1) {
        int q = tid - (400 * DIN + 400 + DIN * HID);
        if (q < NCHUNK)               g_flag1[q] = 0;
        else if (q < NCHUNK + NXTILE) g_flag0[q - NCHUNK] = 0;
        else                          g_prog0 = 0;
    }
}

// ---------------- xp0 producer (blocks 10..73) ------------------------------
__device__ void xp0_producer(int pb, const float* __restrict__ inputs) {
    __shared__ __align__(16) float inpT[DIN * XTILE];   // [k][t], 38.4 KB
    const int j  = threadIdx.x;                         // rows j and j+200
    const int r0 = j, r1 = j + 200;
    const int s0 = xp_slot(r0), s1 = xp_slot(r1);
    const float b0 = g_bc[r0], b1 = g_bc[r1];

    for (int ti = pb; ti < NXTILE; ti += NXPB) {
        const int t0 = ti * XTILE;
        for (int idx = j; idx < XTILE * DIN; idx += THR) {
            int t = idx / DIN, k = idx % DIN;
            inpT[k * XTILE + t] = inputs[(t0 + t) * DIN + k];
        }
        __syncthreads();

        u64 acc0[16], acc1[16];
        #pragma unroll
        for (int tp = 0; tp < 16; tp++) {
            acc0[tp] = packf2(b0, b0);
            acc1[tp] = packf2(b1, b1);
        }
        #pragma unroll 2
        for (int k = 0; k < DIN; k++) {
            float w0 = g_WcT[k * 400 + r0];
            float w1 = g_WcT[k * 400 + r1];
            u64 w02 = packf2(w0, w0), w12 = packf2(w1, w1);
            const u64* row2 = (const u64*)(inpT + k * XTILE);
            #pragma unroll
            for (int tp = 0; tp < 16; tp++) {
                u64 hv = row2[tp];
                acc0[tp] = ffma2(w02, hv, acc0[tp]);
                acc1[tp] = ffma2(w12, hv, acc1[tp]);
            }
        }
        #pragma unroll
        for (int tp = 0; tp < 16; tp++) {
            float lo0 = hsum2(0), hi0;   // placeholders (unpack below)
            float a, b2;
            asm("mov.b64 {%0, %1}, %2;" : "=f"(a), "=f"(b2) : "l"(acc0[tp]));
            g_xp0[(t0 + 2 * tp + 0) * XROW + s0] = a;
            g_xp0[(t0 + 2 * tp + 1) * XROW + s0] = b2;
            asm("mov.b64 {%0, %1}, %2;" : "=f"(a), "=f"(b2) : "l"(acc1[tp]));
            g_xp0[(t0 + 2 * tp + 0) * XROW + s1] = a;
            g_xp0[(t0 + 2 * tp + 1) * XROW + s1] = b2;
            (void)lo0; (void)hi0;
        }
        __threadfence();
        __syncthreads();                                // also protects inpT reuse
        if (j == 0) g_flag0[ti] = 1;
    }
}

// ---------------- layer scan (blocks 0 and 1) -------------------------------
// tid = 2u + p. Lane pair = one hidden unit. Each thread holds ALL 4 gate rows
// restricted to its k-half (p=0: k<50, p=1: k>=50) -> h smem reads halved AND
// warp count halved vs 1-row/thread. Partials recombined with 2 shfl.xor;
// gate product crosses with 1 more shfl; odd lane owns c/h. One bar per step.
template <int L>
__device__ void layer_scan(const float* __restrict__ Whh,
                           const float* __restrict__ xp_src,
                           float* __restrict__ h_dst,
                           float* __restrict__ out) {
    __shared__ __align__(16) float hs[2][112];          // double-buffered h
    const int tid = threadIdx.x;
    const int u   = tid >> 1;
    const int p   = tid & 1;
    const int kb  = p * 50;                             // this lane's k-half
    const unsigned mask = (tid < 192) ? 0xFFFFFFFFu : 0x000000FFu;
    const int lane = tid & 31;
    const float s1c = p ? 1.f : 0.f;                    // a1 = s?sig : 2sig-1
    // rows (PyTorch i,f,g,o): order here [i, g, f, o] = {u, 200+u, 100+u, 300+u}
    u64 w0[25], w1[25], w2[25], w3[25];
    {
        const float* base = Whh + kb;
        #pragma unroll
        for (int q = 0; q < 25; q++) {
            const float* ri = base + u * HID + 2 * q;
            const float* rg = base + (200 + u) * HID + 2 * q;
            const float* rf = base + (100 + u) * HID + 2 * q;
            const float* ro = base + (300 + u) * HID + 2 * q;
            w0[q] = packf2(ri[0], ri[1]);
            w1[q] = packf2(2.f * rg[0], 2.f * rg[1]);   // tanh-as-2sig prescale
            w2[q] = packf2(rf[0], rf[1]);
            w3[q] = packf2(ro[0], ro[1]);
        }
    }
    if (tid < HID) hs[0][tid] = 0.f;
    __syncthreads();

    float c = 0.f, hcur = 0.f;
    const float2* xp_p = ((const float2*)xp_src) + tid; // (t*448 + 4u+2p)/2 = t*224+tid... NO:
    // xp row stride 448 floats = 224 float2; slot pair base = (4u+2p)/2 = 2u+p = tid. OK.
    float2 xc = make_float2(0.f, 0.f), xn = xc;

    for (int cb = 0; cb < TT / 32; cb++) {
        if (tid == 0) {                                 // readiness wait, hoisted
            if (L == 0) {
                int f1 = (cb + 1 < NXTILE) ? cb + 1 : NXTILE - 1;
                while (!(g_flag0[cb] && g_flag0[f1])) __nanosleep(64);
            } else {
                int c0 = cb >> 1;
                int c1 = (c0 + 1 < NCHUNK) ? c0 + 1 : NCHUNK - 1;
                while (!(g_flag1[c0] && g_flag1[c1])) __nanosleep(64);
            }
            __threadfence();
        }
        __syncthreads();
        if (cb == 0) { xc = xp_p[0]; xn = xp_p[224]; }

        for (int tt = 0; tt < 32; tt++) {
            const int t = cb * 32 + tt;
            const u64* hv = (const u64*)(hs[t & 1] + kb);
            u64 a0 = 0ull, a1 = 0ull, a2 = 0ull, a3 = 0ull;
            #pragma unroll
            for (int q = 0; q < 25; q++) {
                u64 hq = hv[q];
                a0 = ffma2(w0[q], hq, a0);
                a1 = ffma2(w1[q], hq, a1);
                a2 = ffma2(w2[q], hq, a2);
                a3 = ffma2(w3[q], hq, a3);
            }
            float2 xf = xp_p[2 * 224];                  // prefetch t+2 (padded)

            float P0 = hsum2(a0), P1 = hsum2(a1), P2 = hsum2(a2), P3 = hsum2(a3);
            // recombine k-halves across the lane pair
            float r0 = __shfl_xor_sync(mask, p ? P0 : P2, 1);
            float r1 = __shfl_xor_sync(mask, p ? P1 : P3, 1);
            float m0 = p ? P2 : P0;
            float m1 = p ? P3 : P1;
            float pre0 = xc.x + m0 + r0;                // A: i   B: f
            float pre1 = xc.y + m1 + r1;                // A: 2g  B: o
            float g0 = sig_(pre0);
            float g1 = sig_(pre1);
            float act1 = fmaf(2.f - s1c, g1, s1c - 1.f); // A: 2sig-1=tanh(g); B: sig(o)
            float prod = g0 * act1;                      // A: ai*ag ; B: af*ao (unused)
            float prodA = __shfl_sync(mask, prod, lane & ~1);

            if (p) {                                    // odd lane owns c/h
                c = fmaf(g0, c, prodA);                 // g0 = a_f
                float th = tanh_(c);
                hcur = act1 * th;                       // act1 = a_o
                hs[(t + 1) & 1][u] = hcur;
                h_dst[t * HID + u] = hcur;
            }
            __syncthreads();                            // single barrier per step

            xc = xn; xn = xf; xp_p += 224;
        }

        if (L == 0) {                                   // publish per 32 steps
            __threadfence();
            __syncthreads();
            if (tid == 0) g_prog0 = (cb + 1) * 32;
        }
    }

    if (p) {                                            // h_n / c_n tails
        out[TT * DIN + L * HID + u]           = hcur;
        out[TT * DIN + 2 * HID + L * HID + u] = c;
    }
}

// ---------------- chaser: xp1 = h0 @ Wih1^T + b (blocks 2..9) --------------
__device__ void chaser(int ci,
                       const float* __restrict__ Wih1,
                       const float* __restrict__ bih1,
                       const float* __restrict__ bhh1) {
    __shared__ __align__(16) float h0s[CH * HID];       // 25.6 KB
    const int j  = threadIdx.x;                         // rows 2j, 2j+1
    const int r0 = 2 * j, r1 = 2 * j + 1;
    const float wsA = (r0 >= 200 && r0 < 300) ? 2.f : 1.f;
    const float wsB = (r1 >= 200 && r1 < 300) ? 2.f : 1.f;

    u64 wA[50], wB[50];
    #pragma unroll
    for (int q = 0; q < 50; q++) {
        wA[q] = packf2(wsA * Wih1[r0 * HID + 2 * q], wsA * Wih1[r0 * HID + 2 * q + 1]);
        wB[q] = packf2(wsB * Wih1[r1 * HID + 2 * q], wsB * Wih1[r1 * HID + 2 * q + 1]);
    }
    const float bA = wsA * (bih1[r0] + bhh1[r0]);
    const float bB = wsB * (bih1[r1] + bhh1[r1]);
    const int sA = xp_slot(r0), sB = xp_slot(r1);

    for (int cidx = ci; cidx < NCHUNK; cidx += NCHASE) {
        const int t0 = cidx * CH;
        if (j == 0) {
            while (g_prog0 < t0 + CH) __nanosleep(128);
            __threadfence();
        }
        __syncthreads();
        {
            const float4* src = (const float4*)(g_h0 + t0 * HID);
            float4*       dst = (float4*)h0s;
            for (int idx = j; idx < CH * HID / 4; idx += THR)
                dst[idx] = src[idx];
        }
        __syncthreads();

        for (int t = 0; t < CH; t++) {
            const u64* hv = (const u64*)(h0s + t * HID);
            u64 aA = 0ull, aB = 0ull;
            #pragma unroll 10
            for (int q = 0; q < 50; q++) {
                u64 hq = hv[q];
                aA = ffma2(wA[q], hq, aA);
                aB = ffma2(wB[q], hq, aB);
            }
            g_xp1[(t0 + t) * XROW + sA] = bA + hsum2(aA);
            g_xp1[(t0 + t) * XROW + sB] = bB + hsum2(aB);
        }
        __threadfence();
        __syncthreads();
        if (j == 0) g_flag1[cidx] = 1;
    }
}

// ---------------- persistent kernel -----------------------------------------
__global__ __launch_bounds__(THR, 1)
void scan_kernel(const float* __restrict__ inputs,
                 const float* __restrict__ Whh0,
                 const float* __restrict__ Wih1,
                 const float* __restrict__ Whh1,
                 const float* __restrict__ bih1,
                 const float* __restrict__ bhh1,
                 float* __restrict__ out) {
    if (blockIdx.x == 0)       layer_scan<0>(Whh0, g_xp0, g_h0, out);
    else if (blockIdx.x == 1)  layer_scan<1>(Whh1, g_xp1, g_h1, out);
    else if (blockIdx.x < 2 + NCHASE) chaser(blockIdx.x - 2, Wih1, bih1, bhh1);
    else                       xp0_producer(blockIdx.x - 2 - NCHASE, inputs);
}

// ---------------- kernel 2: outputs = h1_seq @ W_out^T + b_out -------------
__global__ __launch_bounds__(320) void out_gemm(const float* __restrict__ bout,
                                                float* __restrict__ out) {
    __shared__ __align__(16) float h1s[32 * HID];
    const int t0 = blockIdx.x * 32;
    const int d  = threadIdx.x;

    {
        const float4* src = (const float4*)(g_h1 + t0 * HID);
        float4*       dst = (float4*)h1s;
        for (int idx = threadIdx.x; idx < 32 * HID / 4; idx += 320)
            dst[idx] = src[idx];
    }
    __syncthreads();

    if (d < DIN) {
        u64 w[50];
        #pragma unroll
        for (int kk = 0; kk < 50; kk++)
            w[kk] = packf2(g_WoutT[(2 * kk) * DIN + d], g_WoutT[(2 * kk + 1) * DIN + d]);
        const float bd = bout[d];
        for (int t = 0; t < 32; t++) {
            const u64* hv = (const u64*)(h1s + t * HID);
            u64 a0 = 0ull, a1 = 0ull;
            #pragma unroll 5
            for (int q = 0; q < 25; q++) {
                a0 = ffma2(w[2 * q + 0], hv[2 * q + 0], a0);
                a1 = ffma2(w[2 * q + 1], hv[2 * q + 1], a1);
            }
            out[(t0 + t) * DIN + d] = bd + hsum2(a0) + hsum2(a1);
        }
    }
}

// ---------------- launch ----------------------------------------------------
extern "C" void kernel_launch(void* const* d_in, const int* in_sizes, int n_in,
                              void* d_out, int out_size) {
    (void)in_sizes; (void)n_in; (void)out_size;
    const float* inputs = (const float*)d_in[0];
    const float* W_inp  = (const float*)d_in[1];
    const float* b_inp  = (const float*)d_in[2];
    const float* Wih0   = (const float*)d_in[3];
    const float* Whh0   = (const float*)d_in[4];
    const float* bih0   = (const float*)d_in[5];
    const float* bhh0   = (const float*)d_in[6];
    const float* Wih1   = (const float*)d_in[7];
    const float* Whh1   = (const float*)d_in[8];
    const float* bih1   = (const float*)d_in[9];
    const float* bhh1   = (const float*)d_in[10];
    const float* Wout   = (const float*)d_in[11];
    const float* bout   = (const float*)d_in[12];
    float* out = (float*)d_out;

    int prep_items = 400 * DIN + 400 + DIN * HID + NCHUNK + NXTILE + 1;
    prep_kernel<<<(prep_items + 255) / 256, 256>>>(Wih0, W_inp, b_inp, bih0, bhh0, Wout);
    scan_kernel<<<2 + NCHASE + NXPB, THR>>>(inputs, Whh0, Wih1, Whh1, bih1, bhh1, out);
    out_gemm<<<TT / 32, 320>>>(bout, out);
}